// round 12
// baseline (speedup 1.0000x reference)
#include <cuda_runtime.h>
#include <math.h>

#define VOCAB 50000
#define EMBD  256
#define HID   512
#define BSZ   64
#define SEQ   1024
#define NCTA  96
#define NCTA_A 32

// ---------------- device-global scratch (no allocation APIs used) ----------------
__device__ float g_P[VOCAB * HID];          // projected embedding + layer0 biases (102.4 MB)
__device__ float g_H[2][1024 * BSZ];        // double-buffered [h0(512 rows); h1(512 rows)] x [64 b]
__device__ unsigned g_bar_count;            // grid barrier counter (returns to 0 each barrier)
__device__ unsigned g_bar_gen;              // monotonic generation (graph-replay safe)

typedef unsigned long long ull;

// ---------------- f32x2 helpers (FFMA2 reachable only via PTX) ----------------
__device__ __forceinline__ ull pk2(float x, float y) {
    ull r; asm("mov.b64 %0,{%1,%2};" : "=l"(r) : "f"(x), "f"(y)); return r;
}
__device__ __forceinline__ void upk2(ull v, float& x, float& y) {
    asm("mov.b64 {%0,%1},%2;" : "=f"(x), "=f"(y) : "l"(v));
}
__device__ __forceinline__ void fma2(ull& d, ull a, ull b) {
    asm("fma.rn.f32x2 %0,%1,%2,%0;" : "+l"(d) : "l"(a), "l"(b));
}

// ---------------- grid barrier (all NCTA CTAs co-resident: 1 CTA/SM, 96 <= 148) ----------------
__device__ __forceinline__ void grid_barrier() {
    __threadfence();          // make this thread's global writes visible device-wide
    __syncthreads();          // all threads of the block fenced
    if (threadIdx.x == 0) {
        volatile unsigned* vgen = &g_bar_gen;
        unsigned g = *vgen;   // read generation BEFORE arriving
        unsigned a = atomicAdd(&g_bar_count, 1u);
        if (a == NCTA - 1u) {
            atomicExch(&g_bar_count, 0u);   // reset count first
            __threadfence();
            *vgen = g + 1u;                 // open next generation
        } else {
            while (*vgen == g) { __nanosleep(64); }
        }
        __threadfence();
    }
    __syncthreads();
}

// ---------------- kernel 1: P[v][j] = sum_k emb[v][k]*Wxh0[k][j] + bxh0[j] + bhh0[j] ----------------
__global__ __launch_bounds__(256) void proj_kernel(
    const float* __restrict__ emb, const float* __restrict__ Wxh0,
    const float* __restrict__ bxh0, const float* __restrict__ bhh0)
{
    __shared__ float As[16][136];   // [k][m], padded
    __shared__ float Bs[16][136];   // [k][n], padded
    const int tid = threadIdx.x;
    const int bm = blockIdx.y * 128;
    const int bn = blockIdx.x * 128;
    const int tx = tid & 15;        // n tile (8 cols each)
    const int ty = tid >> 4;        // m tile (8 rows each)

    float acc[8][8];
    #pragma unroll
    for (int i = 0; i < 8; ++i)
        #pragma unroll
        for (int j = 0; j < 8; ++j) acc[i][j] = 0.f;

    for (int k0 = 0; k0 < EMBD; k0 += 16) {
        // load A tile (transposed): 128 m x 16 k
        #pragma unroll
        for (int q = 0; q < 2; ++q) {
            int idx = tid + q * 256;          // 0..511
            int m  = idx >> 2;
            int kq = (idx & 3) * 4;
            int gm = bm + m;
            float4 e = make_float4(0.f, 0.f, 0.f, 0.f);
            if (gm < VOCAB) e = *reinterpret_cast<const float4*>(&emb[gm * EMBD + k0 + kq]);
            As[kq + 0][m] = e.x; As[kq + 1][m] = e.y; As[kq + 2][m] = e.z; As[kq + 3][m] = e.w;
        }
        // load B tile: 16 k x 128 n
        #pragma unroll
        for (int q = 0; q < 2; ++q) {
            int idx = tid + q * 256;
            int kk = idx >> 5;
            int j4 = (idx & 31) * 4;
            *reinterpret_cast<float4*>(&Bs[kk][j4]) =
                *reinterpret_cast<const float4*>(&Wxh0[(k0 + kk) * HID + bn + j4]);
        }
        __syncthreads();
        #pragma unroll
        for (int kk = 0; kk < 16; ++kk) {
            float4 a0 = *reinterpret_cast<const float4*>(&As[kk][ty * 8]);
            float4 a1 = *reinterpret_cast<const float4*>(&As[kk][ty * 8 + 4]);
            float4 b0 = *reinterpret_cast<const float4*>(&Bs[kk][tx * 8]);
            float4 b1 = *reinterpret_cast<const float4*>(&Bs[kk][tx * 8 + 4]);
            float am[8] = {a0.x, a0.y, a0.z, a0.w, a1.x, a1.y, a1.z, a1.w};
            float bv[8] = {b0.x, b0.y, b0.z, b0.w, b1.x, b1.y, b1.z, b1.w};
            #pragma unroll
            for (int i = 0; i < 8; ++i)
                #pragma unroll
                for (int j = 0; j < 8; ++j)
                    acc[i][j] = fmaf(am[i], bv[j], acc[i][j]);
        }
        __syncthreads();
    }

    // epilogue: add biases, store
    float bj[8];
    #pragma unroll
    for (int j = 0; j < 8; ++j) {
        int jg = bn + tx * 8 + j;
        bj[j] = __ldg(&bxh0[jg]) + __ldg(&bhh0[jg]);
    }
    #pragma unroll
    for (int i = 0; i < 8; ++i) {
        int gm = bm + ty * 8 + i;
        if (gm < VOCAB) {
            float4 o0 = make_float4(acc[i][0] + bj[0], acc[i][1] + bj[1], acc[i][2] + bj[2], acc[i][3] + bj[3]);
            float4 o1 = make_float4(acc[i][4] + bj[4], acc[i][5] + bj[5], acc[i][6] + bj[6], acc[i][7] + bj[7]);
            *reinterpret_cast<float4*>(&g_P[gm * HID + bn + tx * 8])     = o0;
            *reinterpret_cast<float4*>(&g_P[gm * HID + bn + tx * 8 + 4]) = o1;
        }
    }
}

// ---------------- per-CTA phase worker ----------------
// ISA=true : job A — h0(p) = tanh(P[x[b,p]] + h0(p-1) @ Whh0).  32 CTAs: 2 b-tiles(32) x 16 j-tiles(32).
// ISA=false: job B — h1(p-1) = tanh([h0(p-1);h1(p-2)] @ [Wxh1;Whh1] + bxh1 + bhh1). 64 CTAs: 4 b-tiles(16) x 16 j-tiles(32).
template <bool ISA>
__device__ __forceinline__ void run_cta(
    float* __restrict__ Wsm, float* __restrict__ HR, int cid,
    const int* __restrict__ xtok,
    const float* __restrict__ Whh0, const float* __restrict__ Wxh1, const float* __restrict__ Whh1,
    const float* __restrict__ bxh1, const float* __restrict__ bhh1)
{
    constexpr int BB     = ISA ? 32 : 16;       // batch cols per CTA
    constexpr int KTOT   = ISA ? 512 : 1024;    // dot length
    constexpr int KT     = ISA ? 16 : 32;       // split-K groups (k-slice = 32)
    constexpr int NBT    = ISA ? 4 : 2;         // b-tiles of 8 per CTA
    constexpr int NOUT   = 32 * BB;             // outputs per CTA (1024 / 512)
    constexpr int STRIDE = NOUT + 8;            // padded reduction row
    constexpr int NI     = NOUT / 256;          // outputs per thread in stage-2
    constexpr int SH     = ISA ? 8 : 7;         // (o >> SH)&3 recovers jt

    const int tid = threadIdx.x;
    const int b0  = ISA ? (cid & 1) * 32 : (cid & 3) * 16;
    const int j0  = ISA ? (cid >> 1) * 32 : (cid >> 2) * 32;

    const int jt  = tid & 3;
    const int bt  = (tid >> 2) & (NBT - 1);
    const int kt  = ISA ? (tid >> 4) : (tid >> 3);
    const int jl0 = jt * 8;
    const int bl0 = bt * 8;
    const int ks  = kt * 32;

    // ---- load weights into SMEM once (constant across all phases) ----
    #pragma unroll
    for (int i = 0; i < KTOT / 32; ++i) {
        int idx = tid + i * 256;
        int k   = idx >> 3;
        int c4  = (idx & 7) << 2;
        const float* src;
        if (ISA) src = &Whh0[k * HID + j0 + c4];
        else     src = (k < 512) ? &Wxh1[k * HID + j0 + c4] : &Whh1[(k - 512) * HID + j0 + c4];
        float4 v = *reinterpret_cast<const float4*>(src);
        int sw = (k & 32) ? 4 : 0;    // XOR-4 swizzle kills kt-pair bank conflicts
        *reinterpret_cast<float4*>(&Wsm[k * 32 + (c4 ^ sw)]) = v;
    }

    for (int p = 0; p <= SEQ; ++p) {
        const float* Hc = &g_H[p & 1][0];
        float*       Hn = &g_H[(p & 1) ^ 1][0];

        // ---- stage state slice into SMEM (L2-coherent reads: L1 stale across grid barrier) ----
        #pragma unroll
        for (int i = 0; i < 16; ++i) {
            int idx = tid + i * 256;
            int k, c4;
            if (ISA) { k = idx >> 3; c4 = (idx & 7) << 2; }
            else     { k = idx >> 2; c4 = (idx & 3) << 2; }
            float4 v = __ldcg(reinterpret_cast<const float4*>(&Hc[k * 64 + b0 + c4]));
            int sw = (k & 32) ? 4 : 0;
            *reinterpret_cast<float4*>(&HR[k * BB + (c4 ^ sw)]) = v;
        }
        __syncthreads();

        // ---- compute: 8j x 8b tile over k-slice of 32, f32x2 FMAs ----
        ull acc[4][8];
        #pragma unroll
        for (int a = 0; a < 4; ++a)
            #pragma unroll
            for (int b = 0; b < 8; ++b) acc[a][b] = 0ULL;

        #pragma unroll 8
        for (int kk = 0; kk < 32; ++kk) {
            int k  = ks + kk;
            int sw = (k & 32) ? 4 : 0;
            ulonglong2 wlo = *reinterpret_cast<const ulonglong2*>(&Wsm[k * 32 + (jl0 ^ sw)]);
            ulonglong2 whi = *reinterpret_cast<const ulonglong2*>(&Wsm[k * 32 + ((jl0 + 4) ^ sw)]);
            float4 ha  = *reinterpret_cast<const float4*>(&HR[k * BB + (bl0 ^ sw)]);
            float4 hb4 = *reinterpret_cast<const float4*>(&HR[k * BB + ((bl0 + 4) ^ sw)]);
            ull hb[8];
            hb[0] = pk2(ha.x, ha.x);   hb[1] = pk2(ha.y, ha.y);
            hb[2] = pk2(ha.z, ha.z);   hb[3] = pk2(ha.w, ha.w);
            hb[4] = pk2(hb4.x, hb4.x); hb[5] = pk2(hb4.y, hb4.y);
            hb[6] = pk2(hb4.z, hb4.z); hb[7] = pk2(hb4.w, hb4.w);
            #pragma unroll
            for (int b = 0; b < 8; ++b) {
                fma2(acc[0][b], wlo.x, hb[b]);
                fma2(acc[1][b], wlo.y, hb[b]);
                fma2(acc[2][b], whi.x, hb[b]);
                fma2(acc[3][b], whi.y, hb[b]);
            }
        }
        __syncthreads();   // everyone done reading HR before it becomes the reduction buffer

        // ---- stage-1: write split-K partials (swizzled: conflict-free) ----
        {
            int rb = kt * STRIDE + 2 * jt + (kt & 1);
            #pragma unroll
            for (int a = 0; a < 4; ++a) {
                int jl = jl0 + 2 * a;
                #pragma unroll
                for (int b = 0; b < 8; ++b) {
                    float lo, hi;
                    upk2(acc[a][b], lo, hi);
                    HR[rb + jl * BB + bl0 + b]       = lo;
                    HR[rb + (jl + 1) * BB + bl0 + b] = hi;
                }
            }
        }
        __syncthreads();

        // ---- stage-2: reduce over KT, fuse epilogue (gather/bias + tanh), coalesced store ----
        #pragma unroll
        for (int i = 0; i < NI; ++i) {
            int o   = tid + i * 256;
            int off = o + 2 * ((o >> SH) & 3);
            float s = 0.f;
            #pragma unroll
            for (int q = 0; q < KT; ++q)
                s += HR[q * STRIDE + off + (q & 1)];
            int jl = ISA ? (o >> 5) : (o >> 4);
            int bl = o & (BB - 1);
            int jg = j0 + jl;
            int bg = b0 + bl;
            if (ISA) {
                if (p < SEQ) {
                    int tok = __ldg(&xtok[bg * SEQ + p]);
                    Hn[jg * 64 + bg] = tanhf(s + __ldg(&g_P[tok * HID + jg]));
                }
            } else {
                if (p >= 1) {
                    Hn[(512 + jg) * 64 + bg] = tanhf(s + __ldg(&bxh1[jg]) + __ldg(&bhh1[jg]));
                }
            }
        }
        grid_barrier();
    }
}

// ---------------- kernel 2: persistent pipelined RNN ----------------
__global__ __launch_bounds__(256, 1) void rnn_kernel(
    const int* __restrict__ x,
    const float* __restrict__ Whh0,
    const float* __restrict__ Wxh1, const float* __restrict__ Whh1,
    const float* __restrict__ bxh1, const float* __restrict__ bhh1,
    const float* __restrict__ fc_w, const float* __restrict__ fc_b,
    float* __restrict__ out)
{
    extern __shared__ float smem[];

    // zero-init both state buffers (h0(-1)=0, h1(-1)=h1(-2)=0)
    for (int i = blockIdx.x * 256 + threadIdx.x; i < 2 * 1024 * BSZ; i += NCTA * 256)
        (&g_H[0][0])[i] = 0.f;
    grid_barrier();

    if (blockIdx.x < NCTA_A) {
        float* Wsm = smem;                 // 512*32 floats
        float* HR  = smem + 512 * 32;
        run_cta<true>(Wsm, HR, blockIdx.x, x, Whh0, Wxh1, Whh1, bxh1, bhh1);
    } else {
        float* Wsm = smem;                 // 1024*32 floats
        float* HR  = smem + 1024 * 32;
        run_cta<false>(Wsm, HR, blockIdx.x - NCTA_A, x, Whh0, Wxh1, Whh1, bxh1, bhh1);
    }

    // ---- final: out[b] = sigmoid(h1(S-1) . fc_w + fc_b) ; h1(S-1) sits in g_H[1] rows 512+ ----
    if (blockIdx.x == 0) {
        float* red = smem + 512 * 32;     // A-type CTA, HR region free now
        int tid = threadIdx.x;
        int b = tid >> 2, q = tid & 3;
        const float* h1 = &g_H[1][512 * 64];
        float s = 0.f;
        for (int j = q * 128; j < q * 128 + 128; ++j)
            s += __ldcg(&h1[j * 64 + b]) * __ldg(&fc_w[j]);
        red[tid] = s;
        __syncthreads();
        if (q == 0) {
            float z = red[tid] + red[tid + 1] + red[tid + 2] + red[tid + 3] + __ldg(&fc_b[0]);
            out[b] = 1.f / (1.f + expf(-z));
        }
    }
}

// ---------------- launch ----------------
#define RNN_SMEM ((1024 * 32 + 16640) * (int)sizeof(float))   // 197632 B

extern "C" void kernel_launch(void* const* d_in, const int* in_sizes, int n_in,
                              void* d_out, int out_size)
{
    const int*   x    = (const int*)  d_in[0];
    const float* emb  = (const float*)d_in[1];
    const float* Wxh0 = (const float*)d_in[2];
    const float* bxh0 = (const float*)d_in[3];
    const float* Whh0 = (const float*)d_in[4];
    const float* bhh0 = (const float*)d_in[5];
    const float* Wxh1 = (const float*)d_in[6];
    const float* bxh1 = (const float*)d_in[7];
    const float* Whh1 = (const float*)d_in[8];
    const float* bhh1 = (const float*)d_in[9];
    const float* fc_w = (const float*)d_in[10];
    const float* fc_b = (const float*)d_in[11];
    float* out = (float*)d_out;

    cudaFuncSetAttribute(rnn_kernel, cudaFuncAttributeMaxDynamicSharedMemorySize, RNN_SMEM);

    dim3 gp(HID / 128, (VOCAB + 127) / 128);   // 4 x 391
    proj_kernel<<<gp, 256>>>(emb, Wxh0, bxh0, bhh0);
    rnn_kernel<<<NCTA, 256, RNN_SMEM>>>(x, Whh0, Wxh1, Whh1, bxh1, bhh1, fc_w, fc_b, out);
}

// round 13
// speedup vs baseline: 1.0079x; 1.0079x over previous
#include <cuda_runtime.h>
#include <math.h>

#define VOCAB 50000
#define EMBD  256
#define HID   512
#define BSZ   64
#define SEQ   1024
#define NCTA  96
#define NCTA_A 32
#define TPB   512

// ---------------- device-global scratch (no allocation APIs used) ----------------
__device__ float g_P[VOCAB * HID];          // projected embedding + layer0 biases (102.4 MB)
__device__ float g_H[2][1024 * BSZ];        // double-buffered [h0(512 rows); h1(512 rows)] x [64 b]
__device__ unsigned g_bar_count;            // grid barrier counter (returns to 0 each barrier)
__device__ unsigned g_bar_gen;              // monotonic generation (graph-replay safe)

typedef unsigned long long ull;

// ---------------- f32x2 helpers (FFMA2 reachable only via PTX) ----------------
__device__ __forceinline__ ull pk2(float x, float y) {
    ull r; asm("mov.b64 %0,{%1,%2};" : "=l"(r) : "f"(x), "f"(y)); return r;
}
__device__ __forceinline__ void upk2(ull v, float& x, float& y) {
    asm("mov.b64 {%0,%1},%2;" : "=f"(x), "=f"(y) : "l"(v));
}
__device__ __forceinline__ void fma2(ull& d, ull a, ull b) {
    asm("fma.rn.f32x2 %0,%1,%2,%0;" : "+l"(d) : "l"(a), "l"(b));
}
__device__ __forceinline__ ull add2(ull a, ull b) {
    ull r; asm("add.rn.f32x2 %0,%1,%2;" : "=l"(r) : "l"(a), "l"(b)); return r;
}

// ---------------- grid barrier (all NCTA CTAs co-resident: 1 CTA/SM, 96 <= 148) ----------------
__device__ __forceinline__ void grid_barrier() {
    __threadfence();          // release this CTA's global writes
    __syncthreads();
    if (threadIdx.x == 0) {
        volatile unsigned* vgen = &g_bar_gen;
        unsigned g = *vgen;   // read generation BEFORE arriving
        unsigned a = atomicAdd(&g_bar_count, 1u);
        if (a == NCTA - 1u) {
            atomicExch(&g_bar_count, 0u);   // reset count first
            __threadfence();
            *vgen = g + 1u;                 // open next generation
        } else {
            while (*vgen == g) { }          // tight poll: wakeup ~ one L2 read
        }
        __threadfence();                    // acquire other CTAs' writes
    }
    __syncthreads();
}

// ---------------- kernel 1: P[v][j] = sum_k emb[v][k]*Wxh0[k][j] + bxh0[j] + bhh0[j] ----------------
__global__ __launch_bounds__(256) void proj_kernel(
    const float* __restrict__ emb, const float* __restrict__ Wxh0,
    const float* __restrict__ bxh0, const float* __restrict__ bhh0)
{
    __shared__ float As[16][136];   // [k][m], padded
    __shared__ float Bs[16][136];   // [k][n], padded
    const int tid = threadIdx.x;
    const int bm = blockIdx.y * 128;
    const int bn = blockIdx.x * 128;
    const int tx = tid & 15;        // n tile (8 cols each)
    const int ty = tid >> 4;        // m tile (8 rows each)

    ull acc2[8][4];                 // 8 m-rows x 4 n-pairs, f32x2 accumulators
    #pragma unroll
    for (int i = 0; i < 8; ++i)
        #pragma unroll
        for (int j = 0; j < 4; ++j) acc2[i][j] = 0ULL;

    for (int k0 = 0; k0 < EMBD; k0 += 16) {
        #pragma unroll
        for (int q = 0; q < 2; ++q) {
            int idx = tid + q * 256;          // 0..511
            int m  = idx >> 2;
            int kq = (idx & 3) * 4;
            int gm = bm + m;
            float4 e = make_float4(0.f, 0.f, 0.f, 0.f);
            if (gm < VOCAB) e = *reinterpret_cast<const float4*>(&emb[gm * EMBD + k0 + kq]);
            As[kq + 0][m] = e.x; As[kq + 1][m] = e.y; As[kq + 2][m] = e.z; As[kq + 3][m] = e.w;
        }
        #pragma unroll
        for (int q = 0; q < 2; ++q) {
            int idx = tid + q * 256;
            int kk = idx >> 5;
            int j4 = (idx & 31) * 4;
            *reinterpret_cast<float4*>(&Bs[kk][j4]) =
                *reinterpret_cast<const float4*>(&Wxh0[(k0 + kk) * HID + bn + j4]);
        }
        __syncthreads();
        #pragma unroll
        for (int kk = 0; kk < 16; ++kk) {
            float4 a0 = *reinterpret_cast<const float4*>(&As[kk][ty * 8]);
            float4 a1 = *reinterpret_cast<const float4*>(&As[kk][ty * 8 + 4]);
            ulonglong2 b0 = *reinterpret_cast<const ulonglong2*>(&Bs[kk][tx * 8]);
            ulonglong2 b1 = *reinterpret_cast<const ulonglong2*>(&Bs[kk][tx * 8 + 4]);
            float am[8] = {a0.x, a0.y, a0.z, a0.w, a1.x, a1.y, a1.z, a1.w};
            ull bp[4] = {b0.x, b0.y, b1.x, b1.y};
            #pragma unroll
            for (int i = 0; i < 8; ++i) {
                ull ai = pk2(am[i], am[i]);
                #pragma unroll
                for (int j = 0; j < 4; ++j) fma2(acc2[i][j], ai, bp[j]);
            }
        }
        __syncthreads();
    }

    float bj[8];
    #pragma unroll
    for (int j = 0; j < 8; ++j) {
        int jg = bn + tx * 8 + j;
        bj[j] = __ldg(&bxh0[jg]) + __ldg(&bhh0[jg]);
    }
    #pragma unroll
    for (int i = 0; i < 8; ++i) {
        int gm = bm + ty * 8 + i;
        if (gm < VOCAB) {
            float o[8];
            #pragma unroll
            for (int j = 0; j < 4; ++j) upk2(acc2[i][j], o[2 * j], o[2 * j + 1]);
            float4 o0 = make_float4(o[0] + bj[0], o[1] + bj[1], o[2] + bj[2], o[3] + bj[3]);
            float4 o1 = make_float4(o[4] + bj[4], o[5] + bj[5], o[6] + bj[6], o[7] + bj[7]);
            *reinterpret_cast<float4*>(&g_P[gm * HID + bn + tx * 8])     = o0;
            *reinterpret_cast<float4*>(&g_P[gm * HID + bn + tx * 8 + 4]) = o1;
        }
    }
}

// ---------------- per-CTA phase worker (512 threads) ----------------
// ISA=true : job A — h0(p) = tanh(P[x[b,p]] + h0(p-1) @ Whh0).  32 CTAs: 2 b-tiles(32) x 16 j-tiles(32).
// ISA=false: job B — h1(p-1) = tanh([h0(p-1);h1(p-2)] @ [Wxh1;Whh1] + b). 64 CTAs: 4 b-tiles(16) x 16 j-tiles(32).
template <bool ISA>
__device__ __forceinline__ void run_cta(
    float* __restrict__ Wsm, float* __restrict__ HR, int cid,
    const int* __restrict__ xtok,
    const float* __restrict__ Whh0, const float* __restrict__ Wxh1, const float* __restrict__ Whh1,
    const float* __restrict__ bxh1, const float* __restrict__ bhh1)
{
    constexpr int BB     = ISA ? 32 : 16;       // batch cols per CTA
    constexpr int KTOT   = ISA ? 512 : 1024;    // dot length
    constexpr int KT_EFF = 16;                  // k-groups AFTER warp pre-reduction
    constexpr int NBT    = ISA ? 4 : 2;         // b-tiles of 8 per CTA
    constexpr int NOUT   = 32 * BB;             // outputs per CTA (1024 / 512)
    constexpr int STRIDE = NOUT + 8;            // padded reduction row
    constexpr int NI     = NOUT / TPB;          // outputs per thread in stage-2 (A:2, B:1)
    constexpr int SH     = ISA ? 8 : 7;         // (o >> SH)&3 recovers jt

    const int tid = threadIdx.x;
    const int b0  = ISA ? (cid & 1) * 32 : (cid & 3) * 16;
    const int j0  = ISA ? (cid >> 1) * 32 : (cid >> 2) * 32;

    const int jt  = tid & 3;
    const int bt  = (tid >> 2) & (NBT - 1);
    const int kt  = ISA ? (tid >> 4) : (tid >> 3);   // A:0..31, B:0..63 (k-slice = 16)
    const int wrp = tid >> 5;                        // effective k-group after shuffle reduce
    const int jl0 = jt * 8;
    const int bl0 = bt * 8;
    const int ks  = kt * 16;
    const bool writer = ISA ? (((tid >> 4) & 1) == 0) : (((tid >> 3) & 3) == 0);

    // ---- load weights into SMEM once (constant across all phases) ----
    #pragma unroll
    for (int i = 0; i < KTOT / 64; ++i) {
        int idx = tid + i * TPB;
        int k   = idx >> 3;
        int c4  = (idx & 7) << 2;
        const float* src;
        if (ISA) src = &Whh0[k * HID + j0 + c4];
        else     src = (k < 512) ? &Wxh1[k * HID + j0 + c4] : &Whh1[(k - 512) * HID + j0 + c4];
        float4 v = *reinterpret_cast<const float4*>(src);
        int sw = (k & 16) ? 4 : 0;    // XOR-4 swizzle keyed on k&16 (warp kt-neighbors differ by 16)
        *reinterpret_cast<float4*>(&Wsm[k * 32 + (c4 ^ sw)]) = v;
    }

    for (int p = 0; p <= SEQ; ++p) {
        const float* Hc = &g_H[p & 1][0];
        float*       Hn = &g_H[(p & 1) ^ 1][0];

        // ---- stage state slice into SMEM (L2-coherent reads: L1 stale across grid barrier) ----
        #pragma unroll
        for (int i = 0; i < 8; ++i) {
            int idx = tid + i * TPB;
            int k, c4;
            if (ISA) { k = idx >> 3; c4 = (idx & 7) << 2; }
            else     { k = idx >> 2; c4 = (idx & 3) << 2; }
            float4 v = __ldcg(reinterpret_cast<const float4*>(&Hc[k * 64 + b0 + c4]));
            int sw = (k & 16) ? 4 : 0;
            *reinterpret_cast<float4*>(&HR[k * BB + (c4 ^ sw)]) = v;
        }
        __syncthreads();

        // ---- compute: 8j x 8b tile over k-slice of 16, f32x2 FMAs ----
        ull acc[4][8];
        #pragma unroll
        for (int a = 0; a < 4; ++a)
            #pragma unroll
            for (int b = 0; b < 8; ++b) acc[a][b] = 0ULL;

        #pragma unroll
        for (int kk = 0; kk < 16; ++kk) {
            int k  = ks + kk;
            int sw = (k & 16) ? 4 : 0;
            ulonglong2 wlo = *reinterpret_cast<const ulonglong2*>(&Wsm[k * 32 + (jl0 ^ sw)]);
            ulonglong2 whi = *reinterpret_cast<const ulonglong2*>(&Wsm[k * 32 + ((jl0 + 4) ^ sw)]);
            float4 ha  = *reinterpret_cast<const float4*>(&HR[k * BB + (bl0 ^ sw)]);
            float4 hb4 = *reinterpret_cast<const float4*>(&HR[k * BB + ((bl0 + 4) ^ sw)]);
            ull hb[8];
            hb[0] = pk2(ha.x, ha.x);   hb[1] = pk2(ha.y, ha.y);
            hb[2] = pk2(ha.z, ha.z);   hb[3] = pk2(ha.w, ha.w);
            hb[4] = pk2(hb4.x, hb4.x); hb[5] = pk2(hb4.y, hb4.y);
            hb[6] = pk2(hb4.z, hb4.z); hb[7] = pk2(hb4.w, hb4.w);
            #pragma unroll
            for (int b = 0; b < 8; ++b) {
                fma2(acc[0][b], wlo.x, hb[b]);
                fma2(acc[1][b], wlo.y, hb[b]);
                fma2(acc[2][b], whi.x, hb[b]);
                fma2(acc[3][b], whi.y, hb[b]);
            }
        }

        // ---- warp pre-reduction over kt-neighbors (keeps split-K buffer at 16 groups) ----
        #pragma unroll
        for (int a = 0; a < 4; ++a)
            #pragma unroll
            for (int b = 0; b < 8; ++b) {
                if (!ISA) acc[a][b] = add2(acc[a][b], __shfl_xor_sync(0xFFFFFFFFu, acc[a][b], 8));
                acc[a][b] = add2(acc[a][b], __shfl_xor_sync(0xFFFFFFFFu, acc[a][b], 16));
            }

        __syncthreads();   // everyone done reading HR before it becomes the reduction buffer

        // ---- stage-1: write split-K partials (swizzled: conflict-free) ----
        if (writer) {
            int rb = wrp * STRIDE + 2 * jt + (wrp & 1);
            #pragma unroll
            for (int a = 0; a < 4; ++a) {
                int jl = jl0 + 2 * a;
                #pragma unroll
                for (int b = 0; b < 8; ++b) {
                    float lo, hi;
                    upk2(acc[a][b], lo, hi);
                    HR[rb + jl * BB + bl0 + b]       = lo;
                    HR[rb + (jl + 1) * BB + bl0 + b] = hi;
                }
            }
        }
        __syncthreads();

        // ---- stage-2: reduce over KT_EFF, fuse epilogue (gather/bias + tanh), coalesced store ----
        #pragma unroll
        for (int i = 0; i < NI; ++i) {
            int o   = tid + i * TPB;
            int off = o + 2 * ((o >> SH) & 3);
            float s = 0.f;
            #pragma unroll
            for (int q = 0; q < KT_EFF; ++q)
                s += HR[q * STRIDE + off + (q & 1)];
            int jl = ISA ? (o >> 5) : (o >> 4);
            int bl = o & (BB - 1);
            int jg = j0 + jl;
            int bg = b0 + bl;
            if (ISA) {
                if (p < SEQ) {
                    int tok = __ldg(&xtok[bg * SEQ + p]);
                    Hn[jg * 64 + bg] = tanhf(s + __ldg(&g_P[tok * HID + jg]));
                }
            } else {
                if (p >= 1) {
                    Hn[(512 + jg) * 64 + bg] = tanhf(s + __ldg(&bxh1[jg]) + __ldg(&bhh1[jg]));
                }
            }
        }
        grid_barrier();
    }
}

// ---------------- kernel 2: persistent pipelined RNN ----------------
__global__ __launch_bounds__(TPB, 1) void rnn_kernel(
    const int* __restrict__ x,
    const float* __restrict__ Whh0,
    const float* __restrict__ Wxh1, const float* __restrict__ Whh1,
    const float* __restrict__ bxh1, const float* __restrict__ bhh1,
    const float* __restrict__ fc_w, const float* __restrict__ fc_b,
    float* __restrict__ out)
{
    extern __shared__ float smem[];

    // zero-init both state buffers (h0(-1)=0, h1(-1)=h1(-2)=0)
    for (int i = blockIdx.x * TPB + threadIdx.x; i < 2 * 1024 * BSZ; i += NCTA * TPB)
        (&g_H[0][0])[i] = 0.f;
    grid_barrier();

    if (blockIdx.x < NCTA_A) {
        float* Wsm = smem;                 // 512*32 floats (64 KB)
        float* HR  = smem + 512 * 32;      // max(16384 staging, 16*1032 stage1) = 16512 floats
        run_cta<true>(Wsm, HR, blockIdx.x, x, Whh0, Wxh1, Whh1, bxh1, bhh1);
    } else {
        float* Wsm = smem;                 // 1024*32 floats (128 KB)
        float* HR  = smem + 1024 * 32;     // max(16384 staging, 16*520 stage1) = 16384 floats
        run_cta<false>(Wsm, HR, blockIdx.x - NCTA_A, x, Whh0, Wxh1, Whh1, bxh1, bhh1);
    }

    // ---- final: out[b] = sigmoid(h1(S-1) . fc_w + fc_b) ; h1(S-1) sits in g_H[1] rows 512+ ----
    if (blockIdx.x == 0 && threadIdx.x < 256) {
        float* red = smem + 512 * 32;     // A-type CTA, HR region free now
        int tid = threadIdx.x;
        int b = tid >> 2, q = tid & 3;
        const float* h1 = &g_H[1][512 * 64];
        float s = 0.f;
        for (int j = q * 128; j < q * 128 + 128; ++j)
            s += __ldcg(&h1[j * 64 + b]) * __ldg(&fc_w[j]);
        red[tid] = s;
        __syncwarp();
        __threadfence_block();
        if (q == 0) {
            float z = red[tid] + red[tid + 1] + red[tid + 2] + red[tid + 3] + __ldg(&fc_b[0]);
            out[b] = 1.f / (1.f + expf(-z));
        }
    }
}

// ---------------- launch ----------------
#define RNN_SMEM ((1024 * 32 + 16512) * (int)sizeof(float))   // 197184 B

extern "C" void kernel_launch(void* const* d_in, const int* in_sizes, int n_in,
                              void* d_out, int out_size)
{
    const int*   x    = (const int*)  d_in[0];
    const float* emb  = (const float*)d_in[1];
    const float* Wxh0 = (const float*)d_in[2];
    const float* bxh0 = (const float*)d_in[3];
    const float* Whh0 = (const float*)d_in[4];
    const float* bhh0 = (const float*)d_in[5];
    const float* Wxh1 = (const float*)d_in[6];
    const float* bxh1 = (const float*)d_in[7];
    const float* Whh1 = (const float*)d_in[8];
    const float* bhh1 = (const float*)d_in[9];
    const float* fc_w = (const float*)d_in[10];
    const float* fc_b = (const float*)d_in[11];
    float* out = (float*)d_out;

    cudaFuncSetAttribute(rnn_kernel, cudaFuncAttributeMaxDynamicSharedMemorySize, RNN_SMEM);

    dim3 gp(HID / 128, (VOCAB + 127) / 128);   // 4 x 391
    proj_kernel<<<gp, 256>>>(emb, Wxh0, bxh0, bhh0);
    rnn_kernel<<<NCTA, TPB, RNN_SMEM>>>(x, Whh0, Wxh1, Whh1, bxh1, bhh1, fc_w, fc_b, out);
}